// round 11
// baseline (speedup 1.0000x reference)
#include <cuda_runtime.h>
#include <float.h>

// YOLOv3 detection-head decode, fused single pass. One thread per CELL PAIR.
//
// R10 -> R11: vectorize loads to float2 (2 adjacent cells per thread).
// Occupancy is no longer scarce (4-7x the needed latency hiding), but LSU
// issue (~85 scalar LDG/thread) was the largest identified warm cost term.
// float2 halves per-byte load-issue and total instruction count. 29 warps/SM
// with 8-deep float2 batches (2KB/warp in flight) still far exceeds the
// ~10KB/SM BW-delay product.
//
// Kept from R10 winner: 80MB evict_last range pin on the input (stable,
// deterministic L2 residency across graph replays), trailing input +
// all outputs evict_first; smem-staged float4-coalesced pred writeback;
// exact grid (1083 x 128).
//
// Algebraic simplification: sigmoid is monotonic ->
//   max(sigmoid(cls)) == sigmoid(max(cls)), argmax(sigmoid(cls)) == argmax(cls).

#define HWV     5776      // 76*76  (even: cell pairs never straddle a plane)
#define WV      76        // even: pairs never straddle a row
#define HV      76
#define ATTRS   85
#define NCLS    80
#define NMASK   3
#define VAL_CONF 0.1f
#define PIN_BYTES (80u * 1024u * 1024u)

__device__ __forceinline__ float sigmoidf(float v) {
    return 1.0f / (1.0f + __expf(-v));
}

__device__ __forceinline__ unsigned long long mk_range_policy(
    const float* __restrict__ base, unsigned int primary, unsigned int total) {
    unsigned long long pol;
    asm("createpolicy.range.global.L2::evict_last.L2::evict_first.b64 %0, [%1], %2, %3;"
        : "=l"(pol) : "l"(base), "r"(primary), "r"(total));
    return pol;
}

// Read-only float2 load with the range policy applied.
__device__ __forceinline__ float2 ldg2_pol(const float* __restrict__ p,
                                           unsigned long long pol) {
    float2 v;
    asm("ld.global.nc.L2::cache_hint.v2.f32 {%0, %1}, [%2], %3;"
        : "=f"(v.x), "=f"(v.y) : "l"(p), "l"(pol));
    return v;
}

__global__ void __launch_bounds__(128, 8)
yolo_head_kernel(const float* __restrict__ x,
                 const float* __restrict__ anchors,
                 float* __restrict__ out,
                 int npairs,             // ncells / 2
                 long long pred_elems,   // ncells * 7
                 unsigned int in_bytes)  // total input bytes
{
    __shared__ float sp[4][448];        // per-warp staging: 64 cells x 7 attrs

    int g    = blockIdx.x * blockDim.x + threadIdx.x;   // exact grid: no tail
    int lane = threadIdx.x & 31;
    int wrp  = threadIdx.x >> 5;

    int c0    = g * 2;                  // first cell of this thread's pair
    int plane = c0 / HWV;
    int idx   = c0 - plane * HWV;       // even
    int m     = plane % NMASK;
    int h     = idx / WV;
    int w     = idx - h * WV;           // even; cells (w, w+1)

    const float* p = x + (size_t)plane * (ATTRS * HWV) + idx;   // 8B-aligned
    unsigned int primary = (in_bytes < PIN_BYTES) ? in_bytes : PIN_BYTES;
    const unsigned long long pol = mk_range_policy(x, primary, in_bytes);

    // Attributes 0..4 as float2 — independent coalesced 256B/warp streams.
    float2 tx = ldg2_pol(p + 0 * HWV, pol);
    float2 ty = ldg2_pol(p + 1 * HWV, pol);
    float2 tw = ldg2_pol(p + 2 * HWV, pol);
    float2 th = ldg2_pol(p + 3 * HWV, pol);
    float2 tc = ldg2_pol(p + 4 * HWV, pol);

    // Class max/argmax over raw logits, per component. 8-deep float2 batches
    // land in registers before any compare consumes them (MLP=8, 2KB/warp).
    // 2 independent chains per cell (even/odd class) for ALU ILP; strict '>'
    // keeps first occurrence within each chain.
    float bx0 = -FLT_MAX, bx1 = -FLT_MAX, by0 = -FLT_MAX, by1 = -FLT_MAX;
    int   ix0 = 0, ix1 = 0, iy0 = 0, iy1 = 0;

    #pragma unroll
    for (int a0 = 0; a0 < NCLS; a0 += 8) {
        float2 v[8];
        #pragma unroll
        for (int j = 0; j < 8; j++)
            v[j] = ldg2_pol(p + (size_t)(5 + a0 + j) * HWV, pol);
        #pragma unroll
        for (int j = 0; j < 8; j += 2) {
            int a = a0 + j;
            if (v[j].x     > bx0) { bx0 = v[j].x;     ix0 = a;     }
            if (v[j + 1].x > bx1) { bx1 = v[j + 1].x; ix1 = a + 1; }
            if (v[j].y     > by0) { by0 = v[j].y;     iy0 = a;     }
            if (v[j + 1].y > by1) { by1 = v[j + 1].y; iy1 = a + 1; }
        }
    }
    // Exact first-occurrence merge (matches jnp.argmax tie-break).
    float bestx = bx0; int bidxx = ix0;
    if (bx1 > bestx || (bx1 == bestx && ix1 < bidxx)) { bestx = bx1; bidxx = ix1; }
    float besty = by0; int bidxy = iy0;
    if (by1 > besty || (by1 == besty && iy1 < bidxy)) { besty = by1; bidxy = iy1; }

    float aw = __ldg(&anchors[2 * m + 0]);
    float ah = __ldg(&anchors[2 * m + 1]);
    const float invW = 1.0f / (float)WV;
    const float invH = 1.0f / (float)HV;

    float* sw_ = sp[wrp];
    float sx, sy;
    {   // cell 0 (.x)
        float cx   = (sigmoidf(tx.x) + (float)w) * invW;
        float cy   = (sigmoidf(ty.x) + (float)h) * invH;
        float bw   = __expf(tw.x) * aw;
        float bh   = __expf(th.x) * ah;
        float conf = sigmoidf(tc.x);
        float cls  = sigmoidf(bestx);
        sx = (conf > VAL_CONF) ? 1.0f : 0.0f;
        float* o = sw_ + lane * 14;
        o[0] = (cx - bw * 0.5f) * sx;
        o[1] = (cy - bh * 0.5f) * sx;
        o[2] = (cx + bw * 0.5f) * sx;
        o[3] = (cy + bh * 0.5f) * sx;
        o[4] = conf * sx;
        o[5] = cls * sx;
        o[6] = (float)bidxx * sx;
    }
    {   // cell 1 (.y)
        float cx   = (sigmoidf(tx.y) + (float)(w + 1)) * invW;
        float cy   = (sigmoidf(ty.y) + (float)h)       * invH;
        float bw   = __expf(tw.y) * aw;
        float bh   = __expf(th.y) * ah;
        float conf = sigmoidf(tc.y);
        float cls  = sigmoidf(besty);
        sy = (conf > VAL_CONF) ? 1.0f : 0.0f;
        float* o = sw_ + lane * 14 + 7;
        o[0] = (cx - bw * 0.5f) * sy;
        o[1] = (cy - bh * 0.5f) * sy;
        o[2] = (cx + bw * 0.5f) * sy;
        o[3] = (cy + bh * 0.5f) * sy;
        o[4] = conf * sy;
        o[5] = cls * sy;
        o[6] = (float)bidxy * sy;
    }
    __syncwarp();

    // Coalesced float4 writeback of the warp's contiguous 1792B pred region
    // (64 cells * 7 floats; warp base = 64-cell aligned -> 1792B aligned).
    int cbase = c0 - 2 * lane;          // first cell of this warp
    float* obase = out + (long long)cbase * 7;
    #pragma unroll
    for (int j = lane; j < 112; j += 32) {
        float4 v4 = *(const float4*)&sw_[j * 4];
        __stcs((float4*)(obase + j * 4), v4);
    }

    // valid: float2 store (c0 even -> 8B aligned).
    __stcs((float2*)&out[pred_elems + c0], make_float2(sx, sy));
}

extern "C" void kernel_launch(void* const* d_in, const int* in_sizes, int n_in,
                              void* d_out, int out_size)
{
    const float* x       = (const float*)d_in[0];
    const float* anchors = (const float*)d_in[1];
    float*       out     = (float*)d_out;

    int nplanes = in_sizes[0] / (ATTRS * HWV);          // bs * 3
    int ncells  = nplanes * HWV;                        // 277248
    int npairs  = ncells / 2;                           // 138624
    long long pred_elems = (long long)ncells * 7;
    unsigned int in_bytes = (unsigned int)in_sizes[0] * 4u;

    int block = 128;
    int grid  = npairs / block;                         // 1083, exact
    yolo_head_kernel<<<grid, block>>>(x, anchors, out, npairs, pred_elems, in_bytes);
}

// round 12
// speedup vs baseline: 1.0108x; 1.0108x over previous
#include <cuda_runtime.h>
#include <float.h>

// YOLOv3 detection-head decode, fused single pass. One thread per cell.
//
// R11 -> R12: REVERT the float2 pairing (it halved warps/SM -> occ 61%->41%
// -> warm 14.4->14.9; concurrency = warps x MLP is what binds, and warps are
// the scarce factor). Back to the R10 scalar winner, with one variable moved:
// PIN_BYTES 80 MiB -> 84 MiB. Input is 89.9 MiB total; known points:
// 89.9 pinned = thrash, 80 = stable winner. Probing the cap from below.
//
// Range policy: [x, x+84MiB) evict_last (deterministic, address-based ->
// stable resident set across graph replays), trailing input evict_first.
// Outputs are __stcs (evict-first) so they never displace pinned input.
//
// Carried over: block 128 / grid 2166 exact, MLP-16 register load batches,
// 4 independent argmax chains with exact first-occurrence merge, smem-staged
// float4-coalesced stores.
//
// Algebraic simplification: sigmoid is monotonic ->
//   max(sigmoid(cls)) == sigmoid(max(cls)), argmax(sigmoid(cls)) == argmax(cls).

#define HWV     5776      // 76*76
#define WV      76
#define HV      76
#define ATTRS   85
#define NCLS    80
#define NMASK   3
#define VAL_CONF 0.1f
#define PIN_BYTES (84u * 1024u * 1024u)   // pinned evict_last prefix of input

__device__ __forceinline__ float sigmoidf(float v) {
    return 1.0f / (1.0f + __expf(-v));
}

// Range cache policy: [x, x+primary) evict_last, [x+primary, x+total) evict_first.
__device__ __forceinline__ unsigned long long mk_range_policy(
    const float* __restrict__ base, unsigned int primary, unsigned int total) {
    unsigned long long pol;
    asm("createpolicy.range.global.L2::evict_last.L2::evict_first.b64 %0, [%1], %2, %3;"
        : "=l"(pol) : "l"(base), "r"(primary), "r"(total));
    return pol;
}

// Read-only scalar load with the range policy applied.
__device__ __forceinline__ float ldg_pol(const float* __restrict__ p,
                                         unsigned long long pol) {
    float v;
    asm("ld.global.nc.L2::cache_hint.f32 %0, [%1], %2;"
        : "=f"(v) : "l"(p), "l"(pol));
    return v;
}

__global__ void __launch_bounds__(128, 12)
yolo_head_kernel(const float* __restrict__ x,
                 const float* __restrict__ anchors,
                 float* __restrict__ out,
                 int ncells,             // nplanes * HWV
                 long long pred_elems,   // nplanes * HWV * 7
                 unsigned int in_bytes)  // total input bytes
{
    __shared__ float sp[4][224];        // per-warp staging: 32 cells x 7 attrs

    int g    = blockIdx.x * blockDim.x + threadIdx.x;   // exact grid: no tail
    int lane = threadIdx.x & 31;
    int wrp  = threadIdx.x >> 5;

    int plane = g / HWV;
    int idx   = g - plane * HWV;        // cell index within plane
    int m     = plane % NMASK;          // anchor/mask index
    int h     = idx / WV;
    int w     = idx - h * WV;

    const float* p = x + (size_t)plane * (ATTRS * HWV) + idx;
    unsigned int primary = (in_bytes < PIN_BYTES) ? in_bytes : PIN_BYTES;
    const unsigned long long pol = mk_range_policy(x, primary, in_bytes);

    // Attributes 0..4 — independent coalesced streams, issued up front.
    float tx = ldg_pol(p + 0 * HWV, pol);
    float ty = ldg_pol(p + 1 * HWV, pol);
    float tw = ldg_pol(p + 2 * HWV, pol);
    float th = ldg_pol(p + 3 * HWV, pol);
    float tc = ldg_pol(p + 4 * HWV, pol);

    // Class max/argmax over raw logits. Batches of 16 loads land in a
    // register buffer BEFORE any compare consumes them -> MLP=16 per batch.
    // 4 independent compare chains; strict '>' keeps first occurrence
    // within each chain.
    float b0 = -FLT_MAX, b1 = -FLT_MAX, b2 = -FLT_MAX, b3 = -FLT_MAX;
    int   i0 = 0, i1 = 0, i2 = 0, i3 = 0;

    #pragma unroll
    for (int a0 = 0; a0 < NCLS; a0 += 16) {
        float v[16];
        #pragma unroll
        for (int j = 0; j < 16; j++)
            v[j] = ldg_pol(p + (size_t)(5 + a0 + j) * HWV, pol);
        #pragma unroll
        for (int j = 0; j < 16; j += 4) {
            int a = a0 + j;
            if (v[j + 0] > b0) { b0 = v[j + 0]; i0 = a;     }
            if (v[j + 1] > b1) { b1 = v[j + 1]; i1 = a + 1; }
            if (v[j + 2] > b2) { b2 = v[j + 2]; i2 = a + 2; }
            if (v[j + 3] > b3) { b3 = v[j + 3]; i3 = a + 3; }
        }
    }

    // Exact first-occurrence merge (matches jnp.argmax tie-break).
    float best = b0; int bidx = i0;
    if (b1 > best || (b1 == best && i1 < bidx)) { best = b1; bidx = i1; }
    if (b2 > best || (b2 == best && i2 < bidx)) { best = b2; bidx = i2; }
    if (b3 > best || (b3 == best && i3 < bidx)) { best = b3; bidx = i3; }

    float aw = __ldg(&anchors[2 * m + 0]);
    float ah = __ldg(&anchors[2 * m + 1]);

    const float invW = 1.0f / (float)WV;
    const float invH = 1.0f / (float)HV;

    float cx   = (sigmoidf(tx) + (float)w) * invW;
    float cy   = (sigmoidf(ty) + (float)h) * invH;
    float bw   = __expf(tw) * aw;
    float bh   = __expf(th) * ah;
    float conf = sigmoidf(tc);
    float cls  = sigmoidf(best);
    float s    = (conf > VAL_CONF) ? 1.0f : 0.0f;

    // Stage 7 outputs in smem (stride-7: gcd(7,32)=1 -> conflict-free).
    float* sw_ = sp[wrp];
    sw_[lane * 7 + 0] = (cx - bw * 0.5f) * s;
    sw_[lane * 7 + 1] = (cy - bh * 0.5f) * s;
    sw_[lane * 7 + 2] = (cx + bw * 0.5f) * s;
    sw_[lane * 7 + 3] = (cy + bh * 0.5f) * s;
    sw_[lane * 7 + 4] = conf * s;
    sw_[lane * 7 + 5] = cls * s;
    sw_[lane * 7 + 6] = (float)bidx * s;
    __syncwarp();

    // Coalesced float4 writeback of the warp's contiguous 896B pred region
    // (896 = 7*128 -> warp base is 128B aligned). Evict-first stores.
    int gbase = g - lane;               // first cell of this warp
    float* obase = out + (long long)gbase * 7;
    #pragma unroll
    for (int j = lane; j < 56; j += 32) {
        float4 v4 = *(const float4*)&sw_[j * 4];
        __stcs((float4*)(obase + j * 4), v4);
    }

    __stcs(&out[pred_elems + g], s);
}

extern "C" void kernel_launch(void* const* d_in, const int* in_sizes, int n_in,
                              void* d_out, int out_size)
{
    const float* x       = (const float*)d_in[0];
    const float* anchors = (const float*)d_in[1];
    float*       out     = (float*)d_out;

    int nplanes = in_sizes[0] / (ATTRS * HWV);          // bs * 3
    int ncells  = nplanes * HWV;                        // 277248
    long long pred_elems = (long long)ncells * 7;
    unsigned int in_bytes = (unsigned int)in_sizes[0] * 4u;

    int block = 128;
    int grid  = ncells / block;                         // 2166, exact
    yolo_head_kernel<<<grid, block>>>(x, anchors, out, ncells, pred_elems, in_bytes);
}

// round 14
// speedup vs baseline: 1.0356x; 1.0244x over previous
#include <cuda_runtime.h>
#include <float.h>

// YOLOv3 detection-head decode, fused single pass. One thread per cell.
//
// R12 -> R13: re-tune occupancy-vs-MLP for the PINNED (L2-hit) latency regime.
// The 80MiB evict_last pin means warm loads hit L2 (~234cyc), not DRAM
// (~577cyc): required in-flight lines/SM drops ~2.5x. At 40 regs the regfile
// capped us at 48 warps (regfile frontier: 48*32*40 = 61440 of 65536 regs).
// This round: 32-reg budget (__launch_bounds__(128,16)) -> ~58.5 warps/SM
// from the 2166-CTA grid, with an 8-deep load batch (MLP=8) and 2 argmax
// chains. Concurrency 58x8 = 464 lines >> ~75-170 needed at L2 latency.
//
// Kept: 80MiB evict_last range pin (measured optimum: 64 < 80 > 84),
// trailing input + all outputs evict_first (__stcs), smem-staged
// float4-coalesced pred writeback, exact grid 2166 x 128.
//
// Algebraic simplification: sigmoid is monotonic ->
//   max(sigmoid(cls)) == sigmoid(max(cls)), argmax(sigmoid(cls)) == argmax(cls).

#define HWV     5776      // 76*76
#define WV      76
#define HV      76
#define ATTRS   85
#define NCLS    80
#define NMASK   3
#define VAL_CONF 0.1f
#define PIN_BYTES (80u * 1024u * 1024u)   // pinned evict_last prefix of input

__device__ __forceinline__ float sigmoidf(float v) {
    return 1.0f / (1.0f + __expf(-v));
}

// Range cache policy: [x, x+primary) evict_last, [x+primary, x+total) evict_first.
__device__ __forceinline__ unsigned long long mk_range_policy(
    const float* __restrict__ base, unsigned int primary, unsigned int total) {
    unsigned long long pol;
    asm("createpolicy.range.global.L2::evict_last.L2::evict_first.b64 %0, [%1], %2, %3;"
        : "=l"(pol) : "l"(base), "r"(primary), "r"(total));
    return pol;
}

// Read-only scalar load with the range policy applied.
__device__ __forceinline__ float ldg_pol(const float* __restrict__ p,
                                         unsigned long long pol) {
    float v;
    asm("ld.global.nc.L2::cache_hint.f32 %0, [%1], %2;"
        : "=f"(v) : "l"(p), "l"(pol));
    return v;
}

__global__ void __launch_bounds__(128, 16)
yolo_head_kernel(const float* __restrict__ x,
                 const float* __restrict__ anchors,
                 float* __restrict__ out,
                 int ncells,             // nplanes * HWV
                 long long pred_elems,   // nplanes * HWV * 7
                 unsigned int in_bytes)  // total input bytes
{
    __shared__ float sp[4][224];        // per-warp staging: 32 cells x 7 attrs

    int g    = blockIdx.x * blockDim.x + threadIdx.x;   // exact grid: no tail
    int lane = threadIdx.x & 31;
    int wrp  = threadIdx.x >> 5;

    int plane = g / HWV;
    int idx   = g - plane * HWV;        // cell index within plane
    int m     = plane % NMASK;          // anchor/mask index
    int h     = idx / WV;
    int w     = idx - h * WV;

    const float* p = x + (size_t)plane * (ATTRS * HWV) + idx;
    unsigned int primary = (in_bytes < PIN_BYTES) ? in_bytes : PIN_BYTES;
    const unsigned long long pol = mk_range_policy(x, primary, in_bytes);

    // Attributes 0..4 — independent coalesced streams, issued up front.
    float tx = ldg_pol(p + 0 * HWV, pol);
    float ty = ldg_pol(p + 1 * HWV, pol);
    float tw = ldg_pol(p + 2 * HWV, pol);
    float th = ldg_pol(p + 3 * HWV, pol);
    float tc = ldg_pol(p + 4 * HWV, pol);

    // Class max/argmax over raw logits. 8-deep register batches (MLP=8),
    // 2 independent compare chains (even/odd class) — register-lean for the
    // 32-reg / 58-warp configuration. Strict '>' keeps first occurrence
    // within each chain.
    float b0 = -FLT_MAX, b1 = -FLT_MAX;
    int   i0 = 0, i1 = 0;

    #pragma unroll
    for (int a0 = 0; a0 < NCLS; a0 += 8) {
        float v[8];
        #pragma unroll
        for (int j = 0; j < 8; j++)
            v[j] = ldg_pol(p + (size_t)(5 + a0 + j) * HWV, pol);
        #pragma unroll
        for (int j = 0; j < 8; j += 2) {
            int a = a0 + j;
            if (v[j + 0] > b0) { b0 = v[j + 0]; i0 = a;     }
            if (v[j + 1] > b1) { b1 = v[j + 1]; i1 = a + 1; }
        }
    }

    // Exact first-occurrence merge (matches jnp.argmax tie-break).
    float best = b0; int bidx = i0;
    if (b1 > best || (b1 == best && i1 < bidx)) { best = b1; bidx = i1; }

    float aw = __ldg(&anchors[2 * m + 0]);
    float ah = __ldg(&anchors[2 * m + 1]);

    const float invW = 1.0f / (float)WV;
    const float invH = 1.0f / (float)HV;

    float cx   = (sigmoidf(tx) + (float)w) * invW;
    float cy   = (sigmoidf(ty) + (float)h) * invH;
    float bw   = __expf(tw) * aw;
    float bh   = __expf(th) * ah;
    float conf = sigmoidf(tc);
    float cls  = sigmoidf(best);
    float s    = (conf > VAL_CONF) ? 1.0f : 0.0f;

    // Stage 7 outputs in smem (stride-7: gcd(7,32)=1 -> conflict-free).
    float* sw_ = sp[wrp];
    sw_[lane * 7 + 0] = (cx - bw * 0.5f) * s;
    sw_[lane * 7 + 1] = (cy - bh * 0.5f) * s;
    sw_[lane * 7 + 2] = (cx + bw * 0.5f) * s;
    sw_[lane * 7 + 3] = (cy + bh * 0.5f) * s;
    sw_[lane * 7 + 4] = conf * s;
    sw_[lane * 7 + 5] = cls * s;
    sw_[lane * 7 + 6] = (float)bidx * s;
    __syncwarp();

    // Coalesced float4 writeback of the warp's contiguous 896B pred region
    // (896 = 7*128 -> warp base is 128B aligned). Evict-first stores.
    int gbase = g - lane;               // first cell of this warp
    float* obase = out + (long long)gbase * 7;
    #pragma unroll
    for (int j = lane; j < 56; j += 32) {
        float4 v4 = *(const float4*)&sw_[j * 4];
        __stcs((float4*)(obase + j * 4), v4);
    }

    __stcs(&out[pred_elems + g], s);
}

extern "C" void kernel_launch(void* const* d_in, const int* in_sizes, int n_in,
                              void* d_out, int out_size)
{
    const float* x       = (const float*)d_in[0];
    const float* anchors = (const float*)d_in[1];
    float*       out     = (float*)d_out;

    int nplanes = in_sizes[0] / (ATTRS * HWV);          // bs * 3
    int ncells  = nplanes * HWV;                        // 277248
    long long pred_elems = (long long)ncells * 7;
    unsigned int in_bytes = (unsigned int)in_sizes[0] * 4u;

    int block = 128;
    int grid  = ncells / block;                         // 2166, exact
    yolo_head_kernel<<<grid, block>>>(x, anchors, out, ncells, pred_elems, in_bytes);
}